// round 10
// baseline (speedup 1.0000x reference)
#include <cuda_runtime.h>
#include <math.h>

#define FS        100.0f
#define N_FILT    12
#define N_CH      27
#define FILT_DIM  5
#define BATCH     8
#define T_IN      65536
#define T_OUT     (T_IN - FILT_DIM + 1)    // 65532
#define ROW_F4    (T_OUT / 4)              // 16383 output float4s per row
#define X_F4      (T_IN / 4)               // 16384 input float4s per row
#define SLAB_F4   1024
#define SLABS_PER_BLOCK 4
#define N_SLABGRP 4                        // 16 slabs / 4 per block
#define TWO_PI    6.283185307179586f

__device__ __forceinline__ void stg_v8(float* p, float4 a, float4 b)
{
    asm volatile("st.global.v8.f32 [%0], {%1,%2,%3,%4,%5,%6,%7,%8};"
                 :: "l"(p),
                    "f"(a.x), "f"(a.y), "f"(a.z), "f"(a.w),
                    "f"(b.x), "f"(b.y), "f"(b.z), "f"(b.w)
                 : "memory");
}

__device__ __forceinline__ float4 conv4(float4 u0, float4 u1,
                                        float w0, float w1, float w2,
                                        float w3, float w4)
{
    float4 r;
    r.x = w0*u0.x + w1*u0.y + w2*u0.z + w3*u0.w + w4*u1.x;
    r.y = w0*u0.y + w1*u0.z + w2*u0.w + w3*u1.x + w4*u1.y;
    r.z = w0*u0.z + w1*u0.w + w2*u1.x + w3*u1.y + w4*u1.z;
    r.w = w0*u0.w + w1*u1.x + w2*u1.y + w3*u1.z + w4*u1.w;
    return r;
}

// ---------------------------------------------------------------------------
// Single-wave persistent layout: 864 blocks (4 x 27 x 8), all resident at
// once (6 blocks/SM x 148 SMs = 888 slots). Each block owns 4 consecutive
// slabs of one (batch, channel) row: build filters once, then per slab
// stage input in smem and write 12 filter rows with 128B-aligned v8 stores.
// ---------------------------------------------------------------------------
__global__ __launch_bounds__(256, 6)
void sinc_conv_persist_kernel(const float* __restrict__ x,
                              const float* __restrict__ filt_low,
                              const float* __restrict__ filt_band,
                              float* __restrict__ out)
{
    const int sg = blockIdx.x;         // slab group 0..3
    const int c  = blockIdx.y;
    const int b  = blockIdx.z;
    const int t  = threadIdx.x;

    __shared__ float4 sx[SLAB_F4 + 1];
    __shared__ float  taps[N_FILT * FILT_DIM];

    // ---- build this channel's 12 filters once (threads 0..11) ----
    if (t < N_FILT) {
        const int idx = c * N_FILT + t;
        float beg = fabsf(filt_low[idx]) + (1.0f / FS);
        float end = beg + fabsf(filt_band[idx]);

        float ae0 = TWO_PI * FS * end * (1.0f / FS);
        float ae1 = TWO_PI * FS * end * (2.0f / FS);
        float ab0 = TWO_PI * FS * beg * (1.0f / FS);
        float ab1 = TWO_PI * FS * beg * (2.0f / FS);
        float ye0 = sinf(ae0) / ae0;
        float ye1 = sinf(ae1) / ae1;
        float yb0 = sinf(ab0) / ab0;
        float yb1 = sinf(ab1) / ab1;
        float se = 2.0f * end, sb = 2.0f * beg;

        float bp0 = se * ye1 - sb * yb1;   // taps 0,4
        float bp1 = se * ye0 - sb * yb0;   // taps 1,3
        float bp2 = se       - sb;         // tap 2
        float mx  = fmaxf(bp2, fmaxf(bp1, bp0));

        #pragma unroll
        for (int k = 0; k < FILT_DIM; k++) {
            float n = (float)k * 1.25f;
            float w = 0.42f - 0.5f * cosf(TWO_PI * n * 0.2f)
                            + 0.08f * cosf(2.0f * TWO_PI * n * 0.2f);
            float bp = (k == 2) ? bp2 : ((k == 1 || k == 3) ? bp1 : bp0);
            taps[t * FILT_DIM + k] = (bp / mx) * w;
        }
    }

    const float4* x4row = (const float4*)(x + ((size_t)b * N_CH + c) * T_IN);
    const size_t  rowb0 = ((size_t)(((size_t)b * N_CH + c) * N_FILT)) * T_OUT;

    for (int si = 0; si < SLABS_PER_BLOCK; si++) {
        const int s = sg * SLABS_PER_BLOCK + si;
        const int base = s * SLAB_F4;

        // ---- stage input slab (coalesced) ----
        #pragma unroll
        for (int idx = t; idx < SLAB_F4 + 1; idx += 256) {
            const int g = base + idx;
            sx[idx] = (g < X_F4) ? __ldg(x4row + g)
                                 : make_float4(0.f, 0.f, 0.f, 0.f);
        }
        __syncthreads();

        const int limit = min(SLAB_F4, ROW_F4 - base);

        #pragma unroll
        for (int f = 0; f < N_FILT; f++) {
            const float w0 = taps[f * FILT_DIM + 0];
            const float w1 = taps[f * FILT_DIM + 1];
            const float w2 = taps[f * FILT_DIM + 2];
            const float w3 = taps[f * FILT_DIM + 3];
            const float w4 = taps[f * FILT_DIM + 4];

            const size_t rb = rowb0 + (size_t)f * T_OUT + (size_t)base * 4;
            float* orow = out + rb;
            // shift (in float4s) so orow + 4*sh is 128B aligned
            const int sh = (int)(((128u - (((unsigned)(rb & 31u)) * 4u)) & 127u) >> 4);

            // head
            if (t < sh && t < limit) {
                float4 r = conv4(sx[t], sx[t + 1], w0, w1, w2, w3, w4);
                *(float4*)(orow + 4 * t) = r;
            }

            // main: 32B/thread, 1KB contiguous per warp wavefront
            #pragma unroll
            for (int it = 0; it < 2; it++) {
                const int k = sh + 2 * t + 512 * it;
                if (k + 1 < limit) {
                    float4 u0 = sx[k];
                    float4 u1 = sx[k + 1];
                    float4 u2 = sx[k + 2];
                    float4 r0 = conv4(u0, u1, w0, w1, w2, w3, w4);
                    float4 r1 = conv4(u1, u2, w0, w1, w2, w3, w4);
                    stg_v8(orow + 4 * k, r0, r1);
                } else if (k < limit) {
                    float4 r = conv4(sx[k], sx[k + 1], w0, w1, w2, w3, w4);
                    *(float4*)(orow + 4 * k) = r;
                }
            }
        }
        __syncthreads();   // sx reused next slab
    }
}

extern "C" void kernel_launch(void* const* d_in, const int* in_sizes, int n_in,
                              void* d_out, int out_size)
{
    const float* x         = (const float*)d_in[0];
    const float* filt_low  = (const float*)d_in[1];
    const float* filt_band = (const float*)d_in[2];
    float* out             = (float*)d_out;

    dim3 grid(N_SLABGRP, N_CH, BATCH);   // 4 x 27 x 8 = 864 blocks, single wave
    sinc_conv_persist_kernel<<<grid, 256>>>(x, filt_low, filt_band, out);
}

// round 12
// speedup vs baseline: 1.2162x; 1.2162x over previous
#include <cuda_runtime.h>
#include <math.h>

#define FS        100.0f
#define N_FILT    12
#define N_CH      27
#define FILT_DIM  5
#define BATCH     8
#define T_IN      65536
#define T_OUT     (T_IN - FILT_DIM + 1)   // 65532
#define NVEC      (T_OUT / 4)             // 16383 output float4s per row
#define X_F4      (T_IN / 4)              // 16384 input float4s per row
#define PAIRS     ((NVEC + 1) / 2)        // 8192 pairs per row
#define TWO_PI    6.283185307179586f

// Single 256-bit store: one instruction, warp wavefront = 1KB contiguous.
// Requires 32B-aligned address.
__device__ __forceinline__ void stg_v8(float* p, float4 a, float4 b)
{
    asm volatile("st.global.v8.f32 [%0], {%1,%2,%3,%4,%5,%6,%7,%8};"
                 :: "l"(p),
                    "f"(a.x), "f"(a.y), "f"(a.z), "f"(a.w),
                    "f"(b.x), "f"(b.y), "f"(b.z), "f"(b.w)
                 : "memory");
}

__device__ __forceinline__ float4 conv4(float4 u0, float4 u1,
                                        float w0, float w1, float w2,
                                        float w3, float w4)
{
    float4 r;
    r.x = w0*u0.x + w1*u0.y + w2*u0.z + w3*u0.w + w4*u1.x;
    r.y = w0*u0.y + w1*u0.z + w2*u0.w + w3*u1.x + w4*u1.y;
    r.z = w0*u0.z + w1*u0.w + w2*u1.x + w3*u1.y + w4*u1.z;
    r.w = w0*u0.w + w1*u1.x + w2*u1.y + w3*u1.z + w4*u1.w;
    return r;
}

// ---------------------------------------------------------------------------
// Register-direct v8 with per-filter alignment classes.
// Row byte length = 262128 ≡ 16 (mod 32) and rowIndex parity == f parity, so:
//   f even: row base 32B-aligned  -> v8 stores at pair k = 2p
//   f odd : row base ≡ 16 mod 32  -> head float4 at k=0 (p==0), v8 at k = 2p+1
// Thread loads 4 input float4s (i0..i0+3) to serve both phases.
// ---------------------------------------------------------------------------
__global__ __launch_bounds__(256)
void sinc_conv_v8_kernel(const float* __restrict__ x,
                         const float* __restrict__ filt_low,
                         const float* __restrict__ filt_band,
                         float* __restrict__ out)
{
    const int c = blockIdx.y;
    const int b = blockIdx.z;

    __shared__ float taps[N_FILT * FILT_DIM];

    if (threadIdx.x < N_FILT) {
        const int f   = threadIdx.x;
        const int idx = c * N_FILT + f;

        float beg = fabsf(filt_low[idx]) + (1.0f / FS);
        float end = beg + fabsf(filt_band[idx]);

        float ae0 = TWO_PI * FS * end * (1.0f / FS);
        float ae1 = TWO_PI * FS * end * (2.0f / FS);
        float ab0 = TWO_PI * FS * beg * (1.0f / FS);
        float ab1 = TWO_PI * FS * beg * (2.0f / FS);
        float ye0 = sinf(ae0) / ae0;
        float ye1 = sinf(ae1) / ae1;
        float yb0 = sinf(ab0) / ab0;
        float yb1 = sinf(ab1) / ab1;
        float se = 2.0f * end, sb = 2.0f * beg;

        float bp0 = se * ye1 - sb * yb1;   // taps 0,4
        float bp1 = se * ye0 - sb * yb0;   // taps 1,3
        float bp2 = se       - sb;         // tap 2
        float mx  = fmaxf(bp2, fmaxf(bp1, bp0));

        #pragma unroll
        for (int k = 0; k < FILT_DIM; k++) {
            float n = (float)k * 1.25f;
            float w = 0.42f - 0.5f * cosf(TWO_PI * n * 0.2f)
                            + 0.08f * cosf(2.0f * TWO_PI * n * 0.2f);
            float bp = (k == 2) ? bp2 : ((k == 1 || k == 3) ? bp1 : bp0);
            taps[f * FILT_DIM + k] = (bp / mx) * w;
        }
    }
    __syncthreads();

    const int p = blockIdx.x * blockDim.x + threadIdx.x;   // pair index
    if (p >= PAIRS) return;
    const int i0 = 2 * p;
    const bool interior = (p < PAIRS - 1);   // p <= 8190: v2, v3 loads valid

    const float4* x4 = (const float4*)(x + ((size_t)b * N_CH + c) * T_IN);
    float4 v0 = __ldg(x4 + i0);
    float4 v1 = __ldg(x4 + i0 + 1);          // i0+1 <= 16383, always valid
    float4 v2, v3;
    if (interior) {
        v2 = __ldg(x4 + i0 + 2);             // <= 16382+... fine for p<=8190
        v3 = __ldg(x4 + i0 + 3);             // i0+3 <= 16383 for p<=8190
    } else {
        v2 = make_float4(0.f, 0.f, 0.f, 0.f);
        v3 = v2;
    }

    float* orow = out + (((size_t)b * N_CH + c) * N_FILT) * T_OUT;

    #pragma unroll
    for (int f = 0; f < N_FILT; f++) {
        const float w0 = taps[f * FILT_DIM + 0];
        const float w1 = taps[f * FILT_DIM + 1];
        const float w2 = taps[f * FILT_DIM + 2];
        const float w3 = taps[f * FILT_DIM + 3];
        const float w4 = taps[f * FILT_DIM + 4];

        float* op = orow + (size_t)f * T_OUT;

        if ((f & 1) == 0) {
            // aligned row: v8 at element 8p
            if (interior) {
                float4 r0 = conv4(v0, v1, w0, w1, w2, w3, w4);
                float4 r1 = conv4(v1, v2, w0, w1, w2, w3, w4);
                stg_v8(op + (size_t)i0 * 4, r0, r1);
            } else {
                // last pair: only float4 index 16382 exists
                float4 r0 = conv4(v0, v1, w0, w1, w2, w3, w4);
                *(float4*)(op + (size_t)i0 * 4) = r0;
            }
        } else {
            // 16-offset row: head at k=0, v8 at k = 2p+1
            if (p == 0) {
                float4 rh = conv4(v0, v1, w0, w1, w2, w3, w4);
                *(float4*)op = rh;
            }
            if (interior) {
                float4 r0 = conv4(v1, v2, w0, w1, w2, w3, w4);
                float4 r1 = conv4(v2, v3, w0, w1, w2, w3, w4);
                stg_v8(op + (size_t)(i0 + 1) * 4, r0, r1);
            }
            // p == PAIRS-1 contributes nothing on odd rows (k=16383 doesn't exist)
        }
    }
}

extern "C" void kernel_launch(void* const* d_in, const int* in_sizes, int n_in,
                              void* d_out, int out_size)
{
    const float* x         = (const float*)d_in[0];
    const float* filt_low  = (const float*)d_in[1];
    const float* filt_band = (const float*)d_in[2];
    float* out             = (float*)d_out;

    dim3 grid((PAIRS + 255) / 256, N_CH, BATCH);   // 32 x 27 x 8 = 6912
    sinc_conv_v8_kernel<<<grid, 256>>>(x, filt_low, filt_band, out);
}